// round 4
// baseline (speedup 1.0000x reference)
#include <cuda_runtime.h>

// Pure 128 MiB D2D copy (output == x exactly; chunked branch of the reference:
// x*0.5 + x*0.5 == x in fp32). R4: route through cudaMemcpyAsync so the graph
// gets a memcpy node (copy-engine / driver-tuned path) instead of an SM copy
// kernel. SM-path plateaued at ~5.75 TB/s (70% of HBM spec) across R1/R3.

extern "C" void kernel_launch(void* const* d_in, const int* in_sizes, int n_in,
                              void* d_out, int out_size) {
    size_t bytes = (size_t)in_sizes[0] * sizeof(float);  // 128 MiB
    cudaMemcpyAsync(d_out, d_in[0], bytes, cudaMemcpyDeviceToDevice, 0);
}